// round 4
// baseline (speedup 1.0000x reference)
#include <cuda_runtime.h>
#include <cuda_fp16.h>

// Problem constants (fixed by the dataset)
constexpr int NN   = 50000;
constexpr int EE   = 1600000;
constexpr int ET   = EE + NN;     // edges + self loops
constexpr int DIN  = 32;
constexpr int HID  = 64;
constexpr int HEADS= 4;
constexpr int F2   = HEADS * HID; // 256
constexpr int DOUT = 32;

// ---------------- scratch (device globals; no allocation allowed) -----------
__device__ __half g_hx [NN * HID];   // x @ W_gcn   (half, gather table)
__device__ float  g_h1 [NN * HID];   // relu(gcn)
__device__ float  g_hg [NN * F2];    // h1 @ W_gat  (fp32, for attdot)
__device__ __half g_hgh[NN * F2];    // h1 @ W_gat  (half, gather table)
__device__ float  g_out2[NN * F2];   // relu(gat)
__device__ float  g_as [NN * HEADS]; // float4-aligned per node
__device__ float  g_ad [NN * HEADS];
__device__ float  g_m  [NN * HEADS]; // softmax max per (node, head)
__device__ float  g_sinv[NN * HEADS];// 1/denom per (node, head)
__device__ float  g_dinv[NN];
__device__ int    g_deg [NN];
__device__ int    g_rowptr[NN + 1];
__device__ int    g_cursor[NN];
__device__ int    g_csr[ET];

// ---------------- CSR build -------------------------------------------------
__global__ void init_kernel() {
    int i = blockIdx.x * blockDim.x + threadIdx.x;
    if (i < NN) { g_deg[i] = 0; g_cursor[i] = 0; }
}

__global__ void deg_kernel(const int* __restrict__ ei) {
    int i = blockIdx.x * blockDim.x + threadIdx.x;
    if (i >= EE) return;
    int d = ei[EE + i];
    d = min(max(d, 0), NN - 1);             // defensive clamp
    atomicAdd(&g_deg[d], 1);
}

// single-block exclusive scan over (deg+1) -> rowptr; also dinv
__global__ void scan_kernel() {
    __shared__ int sh[1024];
    const int C = 49;                       // 1024*49 = 50176 >= NN
    int t = threadIdx.x;
    int start = t * C;
    int end   = min(start + C, NN);
    int sum = 0;
    for (int i = start; i < end; ++i) sum += g_deg[i] + 1;
    sh[t] = sum;
    __syncthreads();
    for (int off = 1; off < 1024; off <<= 1) {
        int v = (t >= off) ? sh[t - off] : 0;
        __syncthreads();
        sh[t] += v;
        __syncthreads();
    }
    int run = sh[t] - sum;                  // exclusive prefix
    for (int i = start; i < end; ++i) {
        g_rowptr[i] = run;
        int d = g_deg[i] + 1;
        g_dinv[i] = rsqrtf((float)d);
        run += d;
    }
    if (t == 1023) g_rowptr[NN] = sh[1023];
}

// fill edges at rowptr[dst]+cursor, self-loop at rowptr[dst+1]-1 (disjoint)
__global__ void csr_fill_kernel(const int* __restrict__ ei) {
    int i = blockIdx.x * blockDim.x + threadIdx.x;
    if (i >= ET) return;
    if (i < EE) {
        int src = min(max(ei[i], 0), NN - 1);
        int dst = min(max(ei[EE + i], 0), NN - 1);
        int pos = g_rowptr[dst] + atomicAdd(&g_cursor[dst], 1);
        g_csr[pos] = src;
    } else {
        int node = i - EE;
        g_csr[g_rowptr[node + 1] - 1] = node;
    }
}

// ---------------- GEMM 1: hx = x @ W_gcn  (50000x32 @ 32x64), half out ------
__global__ void gemm1_kernel(const float* __restrict__ x,
                             const float* __restrict__ W) {
    __shared__ float Wsh[DIN * HID];        // 8 KB
    for (int i = threadIdx.x; i < DIN * HID; i += blockDim.x) Wsh[i] = W[i];
    __syncthreads();
    int gt   = blockIdx.x * blockDim.x + threadIdx.x;
    int warp = gt >> 5;
    int lane = gt & 31;
    if (warp >= NN) return;
    float xv = x[warp * DIN + lane];
    float a0 = 0.f, a1 = 0.f;
#pragma unroll
    for (int k = 0; k < 32; ++k) {
        float xk = __shfl_sync(0xffffffffu, xv, k);
        a0 += xk * Wsh[k * HID + lane];
        a1 += xk * Wsh[k * HID + 32 + lane];
    }
    g_hx[warp * HID + lane]      = __float2half(a0);
    g_hx[warp * HID + 32 + lane] = __float2half(a1);
}

// ---------------- GCN aggregation: one warp per dst node, half gathers ------
__global__ void gcn_agg_kernel(const float* __restrict__ b_gcn) {
    int gt   = blockIdx.x * blockDim.x + threadIdx.x;
    int warp = gt >> 5;
    if (warp >= NN) return;
    int lane = gt & 31;
    int beg = g_rowptr[warp], end = g_rowptr[warp + 1];
    float dd = g_dinv[warp];
    float ax = 0.f, ay = 0.f;
    const __half2* hx2 = (const __half2*)g_hx;
    int j = beg;
    for (; j + 4 <= end; j += 4) {
        int s0 = g_csr[j], s1 = g_csr[j + 1], s2 = g_csr[j + 2], s3 = g_csr[j + 3];
        float w0 = g_dinv[s0] * dd;
        float w1 = g_dinv[s1] * dd;
        float w2 = g_dinv[s2] * dd;
        float w3 = g_dinv[s3] * dd;
        float2 a = __half22float2(hx2[s0 * 32 + lane]);
        float2 b = __half22float2(hx2[s1 * 32 + lane]);
        float2 c = __half22float2(hx2[s2 * 32 + lane]);
        float2 d = __half22float2(hx2[s3 * 32 + lane]);
        ax += a.x * w0 + b.x * w1 + c.x * w2 + d.x * w3;
        ay += a.y * w0 + b.y * w1 + c.y * w2 + d.y * w3;
    }
    for (; j < end; ++j) {
        int s0 = g_csr[j];
        float w0 = g_dinv[s0] * dd;
        float2 a = __half22float2(hx2[s0 * 32 + lane]);
        ax += a.x * w0;
        ay += a.y * w0;
    }
    float2 o;
    o.x = fmaxf(ax + b_gcn[2 * lane],     0.f);
    o.y = fmaxf(ay + b_gcn[2 * lane + 1], 0.f);
    ((float2*)(g_h1 + (size_t)warp * HID))[lane] = o;
}

// ---------------- GEMM 2: hg = h1 @ W_gat (50000x64 @ 64x256) ---------------
__global__ void gemm2_kernel(const float* __restrict__ Wg) {
    __shared__ float Wsh[64 * 128];         // 32 KB (half the columns)
    __shared__ float rsh[4 * 64];
    int tid = threadIdx.x;                  // 128
    int colOff = blockIdx.y * 128;
    for (int q = tid; q < 64 * 128; q += 128) {
        int k = q >> 7, c = q & 127;
        Wsh[q] = Wg[k * F2 + colOff + c];
    }
    __syncthreads();
    int rowBase = blockIdx.x * 64;
    for (int r0 = 0; r0 < 64; r0 += 4) {
        for (int q = tid; q < 256; q += 128) {
            int rr = q >> 6, kk = q & 63;
            int row = rowBase + r0 + rr;
            rsh[q] = (row < NN) ? g_h1[(size_t)row * HID + kk] : 0.f;
        }
        __syncthreads();
        float a0 = 0.f, a1 = 0.f, a2 = 0.f, a3 = 0.f;
#pragma unroll
        for (int k = 0; k < 64; ++k) {
            float w = Wsh[k * 128 + tid];
            a0 += rsh[k]       * w;
            a1 += rsh[64 + k]  * w;
            a2 += rsh[128 + k] * w;
            a3 += rsh[192 + k] * w;
        }
        int row = rowBase + r0;
        if (row < NN) {
            size_t p = (size_t)row * F2 + colOff + tid;
            g_hg[p] = a0;  g_hgh[p] = __float2half(a0);
        }
        if (row + 1 < NN) {
            size_t p = (size_t)(row + 1) * F2 + colOff + tid;
            g_hg[p] = a1;  g_hgh[p] = __float2half(a1);
        }
        if (row + 2 < NN) {
            size_t p = (size_t)(row + 2) * F2 + colOff + tid;
            g_hg[p] = a2;  g_hgh[p] = __float2half(a2);
        }
        if (row + 3 < NN) {
            size_t p = (size_t)(row + 3) * F2 + colOff + tid;
            g_hg[p] = a3;  g_hgh[p] = __float2half(a3);
        }
        __syncthreads();
    }
}

// ---------------- attention dot products (from fp32 hg) ---------------------
__global__ void attdot_kernel(const float* __restrict__ att_src,
                              const float* __restrict__ att_dst) {
    __shared__ float ash[F2], adh[F2];
    int tid = threadIdx.x;                  // 256
    ash[tid] = att_src[tid];
    adh[tid] = att_dst[tid];
    __syncthreads();
    int t = blockIdx.x * blockDim.x + tid;
    if (t >= NN * HEADS) return;
    int n = t >> 2, h = t & 3;
    const float4* row = (const float4*)(g_hg + (size_t)n * F2 + h * HID);
    float ss = 0.f, sd = 0.f;
#pragma unroll
    for (int i = 0; i < 16; ++i) {
        float4 v = row[i];
        int c = h * HID + i * 4;
        ss += v.x * ash[c] + v.y * ash[c + 1] + v.z * ash[c + 2] + v.w * ash[c + 3];
        sd += v.x * adh[c] + v.y * adh[c + 1] + v.z * adh[c + 2] + v.w * adh[c + 3];
    }
    g_as[t] = ss;
    g_ad[t] = sd;
}

__device__ __forceinline__ float lrelu(float e) {
    return (e > 0.f) ? e : 0.2f * e;
}

// ---------------- GAT pass A: per-(node,head) softmax max + denom -----------
__global__ void gat_softmax_kernel() {
    int gt   = blockIdx.x * blockDim.x + threadIdx.x;
    int warp = gt >> 5;
    if (warp >= NN) return;
    int lane = gt & 31;
    int beg = g_rowptr[warp], end = g_rowptr[warp + 1];
    const float4* as4 = (const float4*)g_as;
    float4 ad = as4[0];                     // placeholder; real load below
    ad = ((const float4*)g_ad)[warp];
    float m0 = -3.0e38f, m1 = -3.0e38f, m2 = -3.0e38f, m3 = -3.0e38f;
    float s0 = 0.f, s1 = 0.f, s2 = 0.f, s3 = 0.f;
    for (int j = beg + lane; j < end; j += 32) {
        int src = g_csr[j];
        float4 a = as4[src];
        float e0 = lrelu(a.x + ad.x);
        float e1 = lrelu(a.y + ad.y);
        float e2 = lrelu(a.z + ad.z);
        float e3 = lrelu(a.w + ad.w);
        float n0 = fmaxf(m0, e0); s0 = s0 * __expf(m0 - n0) + __expf(e0 - n0); m0 = n0;
        float n1 = fmaxf(m1, e1); s1 = s1 * __expf(m1 - n1) + __expf(e1 - n1); m1 = n1;
        float n2 = fmaxf(m2, e2); s2 = s2 * __expf(m2 - n2) + __expf(e2 - n2); m2 = n2;
        float n3 = fmaxf(m3, e3); s3 = s3 * __expf(m3 - n3) + __expf(e3 - n3); m3 = n3;
    }
    // butterfly reduce (all lanes converge)
#pragma unroll
    for (int off = 16; off > 0; off >>= 1) {
        float om0 = __shfl_xor_sync(0xffffffffu, m0, off);
        float os0 = __shfl_xor_sync(0xffffffffu, s0, off);
        float om1 = __shfl_xor_sync(0xffffffffu, m1, off);
        float os1 = __shfl_xor_sync(0xffffffffu, s1, off);
        float om2 = __shfl_xor_sync(0xffffffffu, m2, off);
        float os2 = __shfl_xor_sync(0xffffffffu, s2, off);
        float om3 = __shfl_xor_sync(0xffffffffu, m3, off);
        float os3 = __shfl_xor_sync(0xffffffffu, s3, off);
        float n;
        n = fmaxf(m0, om0); s0 = s0 * __expf(m0 - n) + os0 * __expf(om0 - n); m0 = n;
        n = fmaxf(m1, om1); s1 = s1 * __expf(m1 - n) + os1 * __expf(om1 - n); m1 = n;
        n = fmaxf(m2, om2); s2 = s2 * __expf(m2 - n) + os2 * __expf(om2 - n); m2 = n;
        n = fmaxf(m3, om3); s3 = s3 * __expf(m3 - n) + os3 * __expf(om3 - n); m3 = n;
    }
    if (lane < 4) {
        float mv = (lane == 0) ? m0 : (lane == 1) ? m1 : (lane == 2) ? m2 : m3;
        float sv = (lane == 0) ? s0 : (lane == 1) ? s1 : (lane == 2) ? s2 : s3;
        g_m   [warp * HEADS + lane] = mv;
        g_sinv[warp * HEADS + lane] = 1.f / sv;
    }
}

// ---------------- GAT pass B: weighted accumulate (no serial chain) ---------
__global__ void gat_agg_kernel(const float* __restrict__ b_gat) {
    int gt   = blockIdx.x * blockDim.x + threadIdx.x;
    int warp = gt >> 5;
    if (warp >= NN) return;
    int lane = gt & 31;
    int hd   = lane >> 3;                   // head for this lane
    int base = hd * HID + (lane & 7) * 8;   // 8 contiguous features
    float adv  = g_ad  [warp * HEADS + hd];
    float mh   = g_m   [warp * HEADS + hd];
    float sinv = g_sinv[warp * HEADS + hd];
    int beg = g_rowptr[warp], end = g_rowptr[warp + 1];
    float acc[8];
#pragma unroll
    for (int k = 0; k < 8; ++k) acc[k] = 0.f;

    int j = beg;
    for (; j + 4 <= end; j += 4) {
        int s0 = g_csr[j], s1 = g_csr[j + 1], s2 = g_csr[j + 2], s3 = g_csr[j + 3];
        float w0 = __expf(lrelu(g_as[s0 * HEADS + hd] + adv) - mh);
        float w1 = __expf(lrelu(g_as[s1 * HEADS + hd] + adv) - mh);
        float w2 = __expf(lrelu(g_as[s2 * HEADS + hd] + adv) - mh);
        float w3 = __expf(lrelu(g_as[s3 * HEADS + hd] + adv) - mh);
        int4 p0 = *(const int4*)(g_hgh + (size_t)s0 * F2 + base);
        int4 p1 = *(const int4*)(g_hgh + (size_t)s1 * F2 + base);
        int4 p2 = *(const int4*)(g_hgh + (size_t)s2 * F2 + base);
        int4 p3 = *(const int4*)(g_hgh + (size_t)s3 * F2 + base);
        const __half2* h0 = (const __half2*)&p0;
        const __half2* h1 = (const __half2*)&p1;
        const __half2* h2 = (const __half2*)&p2;
        const __half2* h3 = (const __half2*)&p3;
#pragma unroll
        for (int k = 0; k < 4; ++k) {
            float2 a = __half22float2(h0[k]);
            float2 b = __half22float2(h1[k]);
            float2 c = __half22float2(h2[k]);
            float2 d = __half22float2(h3[k]);
            acc[2 * k]     += w0 * a.x + w1 * b.x + w2 * c.x + w3 * d.x;
            acc[2 * k + 1] += w0 * a.y + w1 * b.y + w2 * c.y + w3 * d.y;
        }
    }
    for (; j < end; ++j) {
        int s0 = g_csr[j];
        float w0 = __expf(lrelu(g_as[s0 * HEADS + hd] + adv) - mh);
        int4 p0 = *(const int4*)(g_hgh + (size_t)s0 * F2 + base);
        const __half2* h0 = (const __half2*)&p0;
#pragma unroll
        for (int k = 0; k < 4; ++k) {
            float2 a = __half22float2(h0[k]);
            acc[2 * k]     += w0 * a.x;
            acc[2 * k + 1] += w0 * a.y;
        }
    }
    float* o = g_out2 + (size_t)warp * F2 + base;
#pragma unroll
    for (int k = 0; k < 8; ++k)
        o[k] = fmaxf(acc[k] * sinv + b_gat[base + k], 0.f);
}

// ---------------- GEMM 3: out = out2 @ W_fc + b_fc (50000x256 @ 256x32) -----
__global__ void gemm3_kernel(const float* __restrict__ Wfc,
                             const float* __restrict__ bfc,
                             float* __restrict__ out) {
    __shared__ float Wsh[F2 * DOUT];        // 32 KB
    __shared__ float insh[8 * F2];          //  8 KB
    int tid = threadIdx.x;                  // 256
    for (int q = tid; q < F2 * DOUT; q += 256) Wsh[q] = Wfc[q];
    __syncthreads();
    int rowBase = blockIdx.x * 128;
    int r = tid >> 5, c = tid & 31;
    float bv = bfc[c];
    for (int g = 0; g < 128; g += 8) {
        for (int q = tid; q < 8 * F2; q += 256) {
            int rr = q >> 8, kk = q & 255;
            int row = rowBase + g + rr;
            insh[q] = (row < NN) ? g_out2[(size_t)row * F2 + kk] : 0.f;
        }
        __syncthreads();
        float a = 0.f;
#pragma unroll 8
        for (int k = 0; k < F2; ++k) a += insh[r * F2 + k] * Wsh[k * DOUT + c];
        int row = rowBase + g + r;
        if (row < NN) out[row * DOUT + c] = a + bv;
        __syncthreads();
    }
}

// ---------------- launch ----------------------------------------------------
extern "C" void kernel_launch(void* const* d_in, const int* in_sizes, int n_in,
                              void* d_out, int out_size) {
    const float* x       = (const float*)d_in[0];
    const int*   ei      = (const int*)  d_in[1];   // int32 (JAX x64 off)
    const float* W_gcn   = (const float*)d_in[2];
    const float* b_gcn   = (const float*)d_in[3];
    const float* W_gat   = (const float*)d_in[4];
    const float* att_src = (const float*)d_in[5];
    const float* att_dst = (const float*)d_in[6];
    const float* b_gat   = (const float*)d_in[7];
    const float* W_fc    = (const float*)d_in[8];
    const float* b_fc    = (const float*)d_in[9];
    float*       out     = (float*)d_out;

    init_kernel       <<<(NN + 255) / 256, 256>>>();
    deg_kernel        <<<(EE + 255) / 256, 256>>>(ei);
    scan_kernel       <<<1, 1024>>>();
    csr_fill_kernel   <<<(ET + 255) / 256, 256>>>(ei);

    gemm1_kernel      <<<(NN * 32 + 255) / 256, 256>>>(x, W_gcn);
    gcn_agg_kernel    <<<(NN * 32 + 255) / 256, 256>>>(b_gcn);

    gemm2_kernel      <<<dim3((NN + 63) / 64, 2), 128>>>(W_gat);
    attdot_kernel     <<<(NN * HEADS + 255) / 256, 256>>>(att_src, att_dst);
    gat_softmax_kernel<<<(NN * 32 + 255) / 256, 256>>>();
    gat_agg_kernel    <<<(NN * 32 + 255) / 256, 256>>>(b_gat);

    gemm3_kernel      <<<(NN + 127) / 128, 256>>>(W_fc, b_fc, out);
}

// round 5
// speedup vs baseline: 1.0619x; 1.0619x over previous
#include <cuda_runtime.h>
#include <cuda_fp16.h>

// Problem constants (fixed by the dataset)
constexpr int NN   = 50000;
constexpr int EE   = 1600000;
constexpr int ET   = EE + NN;     // edges + self loops
constexpr int DIN  = 32;
constexpr int HID  = 64;
constexpr int HEADS= 4;
constexpr int F2   = HEADS * HID; // 256
constexpr int DOUT = 32;

// ---------------- scratch (device globals; no allocation allowed) -----------
__device__ __half   g_hx [NN * HID];   // x @ W_gcn  (half gather table)
__device__ float    g_h1 [NN * HID];   // relu(gcn)
__device__ __half   g_hgh[NN * F2];    // h1 @ W_gat (half gather table)
__device__ float    g_out2[NN * F2];   // relu(gat)
__device__ float    g_as [NN * HEADS]; // fp32 attention dots (atomic-accumulated)
__device__ float    g_ad [NN * HEADS];
__device__ unsigned g_maxenc[2 * HEADS]; // [0..3]=max a_s, [4..7]=max a_d (ordered enc)
__device__ float    g_dinv[NN];
__device__ int      g_deg [NN];
__device__ int      g_rowptr[NN + 1];
__device__ int      g_pos [EE];        // position of edge within its dst row
__device__ int      g_csr [ET];

// order-preserving float <-> uint encoding for atomicMax
__device__ __forceinline__ unsigned fenc(float f) {
    unsigned b = __float_as_uint(f);
    return (b & 0x80000000u) ? ~b : (b | 0x80000000u);
}
__device__ __forceinline__ float fdec(unsigned u) {
    return (u & 0x80000000u) ? __uint_as_float(u & 0x7fffffffu)
                             : __uint_as_float(~u);
}

// ---------------- CSR build -------------------------------------------------
__global__ void init_kernel() {
    int i = blockIdx.x * blockDim.x + threadIdx.x;
    if (i < NN) g_deg[i] = 0;
    if (i < NN * HEADS) { g_as[i] = 0.f; g_ad[i] = 0.f; }
    if (i < 2 * HEADS) g_maxenc[i] = 0u;   // minimum key
}

__global__ void deg_kernel(const int* __restrict__ ei) {
    int i = blockIdx.x * blockDim.x + threadIdx.x;
    if (i >= EE) return;
    int d = ei[EE + i];
    d = min(max(d, 0), NN - 1);
    g_pos[i] = atomicAdd(&g_deg[d], 1);    // position within row, no 2nd atomic later
}

// single-block exclusive scan over (deg+1) -> rowptr; also dinv
__global__ void scan_kernel() {
    __shared__ int sh[1024];
    const int C = 49;                       // 1024*49 >= NN
    int t = threadIdx.x;
    int start = t * C;
    int end   = min(start + C, NN);
    int sum = 0;
    for (int i = start; i < end; ++i) sum += g_deg[i] + 1;
    sh[t] = sum;
    __syncthreads();
    for (int off = 1; off < 1024; off <<= 1) {
        int v = (t >= off) ? sh[t - off] : 0;
        __syncthreads();
        sh[t] += v;
        __syncthreads();
    }
    int run = sh[t] - sum;                  // exclusive prefix
    for (int i = start; i < end; ++i) {
        g_rowptr[i] = run;
        int d = g_deg[i] + 1;
        g_dinv[i] = rsqrtf((float)d);
        run += d;
    }
    if (t == 1023) g_rowptr[NN] = sh[1023];
}

// plain scatter: edge -> rowptr[dst]+pos ; self-loop at rowptr[dst+1]-1
__global__ void csr_fill_kernel(const int* __restrict__ ei) {
    int i = blockIdx.x * blockDim.x + threadIdx.x;
    if (i >= ET) return;
    if (i < EE) {
        int src = min(max(ei[i], 0), NN - 1);
        int dst = min(max(ei[EE + i], 0), NN - 1);
        g_csr[g_rowptr[dst] + g_pos[i]] = src;
    } else {
        int node = i - EE;
        g_csr[g_rowptr[node + 1] - 1] = node;
    }
}

// ---------------- GEMM 1: hx = x @ W_gcn  (50000x32 @ 32x64), half out ------
__global__ void gemm1_kernel(const float* __restrict__ x,
                             const float* __restrict__ W) {
    __shared__ float Wsh[DIN * HID];        // 8 KB
    for (int i = threadIdx.x; i < DIN * HID; i += blockDim.x) Wsh[i] = W[i];
    __syncthreads();
    int gt   = blockIdx.x * blockDim.x + threadIdx.x;
    int warp = gt >> 5;
    int lane = gt & 31;
    if (warp >= NN) return;
    float xv = x[warp * DIN + lane];
    float a0 = 0.f, a1 = 0.f;
#pragma unroll
    for (int k = 0; k < 32; ++k) {
        float xk = __shfl_sync(0xffffffffu, xv, k);
        a0 += xk * Wsh[k * HID + lane];
        a1 += xk * Wsh[k * HID + 32 + lane];
    }
    g_hx[warp * HID + lane]      = __float2half(a0);
    g_hx[warp * HID + 32 + lane] = __float2half(a1);
}

// ---------------- GCN aggregation: one warp per dst node, half gathers ------
__global__ void gcn_agg_kernel(const float* __restrict__ b_gcn) {
    int gt   = blockIdx.x * blockDim.x + threadIdx.x;
    int warp = gt >> 5;
    if (warp >= NN) return;
    int lane = gt & 31;
    int beg = g_rowptr[warp], end = g_rowptr[warp + 1];
    float dd = g_dinv[warp];
    float ax = 0.f, ay = 0.f;
    const __half2* hx2 = (const __half2*)g_hx;
    int j = beg;
    for (; j + 4 <= end; j += 4) {
        int s0 = g_csr[j], s1 = g_csr[j + 1], s2 = g_csr[j + 2], s3 = g_csr[j + 3];
        float w0 = g_dinv[s0] * dd;
        float w1 = g_dinv[s1] * dd;
        float w2 = g_dinv[s2] * dd;
        float w3 = g_dinv[s3] * dd;
        float2 a = __half22float2(hx2[s0 * 32 + lane]);
        float2 b = __half22float2(hx2[s1 * 32 + lane]);
        float2 c = __half22float2(hx2[s2 * 32 + lane]);
        float2 d = __half22float2(hx2[s3 * 32 + lane]);
        ax += a.x * w0 + b.x * w1 + c.x * w2 + d.x * w3;
        ay += a.y * w0 + b.y * w1 + c.y * w2 + d.y * w3;
    }
    for (; j < end; ++j) {
        int s0 = g_csr[j];
        float w0 = g_dinv[s0] * dd;
        float2 a = __half22float2(hx2[s0 * 32 + lane]);
        ax += a.x * w0;
        ay += a.y * w0;
    }
    float2 o;
    o.x = fmaxf(ax + b_gcn[2 * lane],     0.f);
    o.y = fmaxf(ay + b_gcn[2 * lane + 1], 0.f);
    ((float2*)(g_h1 + (size_t)warp * HID))[lane] = o;
}

// ---------------- GEMM 2 + fused attention dots -----------------------------
// hg = h1 @ W_gat (50000x64 @ 64x256); stores half table; accumulates
// a_s/a_d partial dot products (fp32) via warp-reduce + atomicAdd.
__global__ void gemm2_kernel(const float* __restrict__ Wg,
                             const float* __restrict__ att_src,
                             const float* __restrict__ att_dst) {
    __shared__ float Wsh[64 * 128];         // 32 KB (half the columns)
    __shared__ float rsh[4 * 64];
    __shared__ float ash[128], adh[128];
    int tid = threadIdx.x;                  // 128
    int colOff = blockIdx.y * 128;
    ash[tid] = att_src[colOff + tid];
    adh[tid] = att_dst[colOff + tid];
    for (int q = tid; q < 64 * 128; q += 128) {
        int k = q >> 7, c = q & 127;
        Wsh[q] = Wg[k * F2 + colOff + c];
    }
    __syncthreads();
    int lane = tid & 31;
    int head = (colOff + (tid & 96)) >> 6;  // head of this warp's columns
    int rowBase = blockIdx.x * 64;
    for (int r0 = 0; r0 < 64; r0 += 4) {
        for (int q = tid; q < 256; q += 128) {
            int rr = q >> 6, kk = q & 63;
            int row = rowBase + r0 + rr;
            rsh[q] = (row < NN) ? g_h1[(size_t)row * HID + kk] : 0.f;
        }
        __syncthreads();
        float a0 = 0.f, a1 = 0.f, a2 = 0.f, a3 = 0.f;
#pragma unroll
        for (int k = 0; k < 64; ++k) {
            float w = Wsh[k * 128 + tid];
            a0 += rsh[k]       * w;
            a1 += rsh[64 + k]  * w;
            a2 += rsh[128 + k] * w;
            a3 += rsh[192 + k] * w;
        }
        float av[4] = {a0, a1, a2, a3};
        int row = rowBase + r0;
#pragma unroll
        for (int rr = 0; rr < 4; ++rr) {
            int r = row + rr;
            if (r < NN) {
                g_hgh[(size_t)r * F2 + colOff + tid] = __float2half(av[rr]);
                float vs = av[rr] * ash[tid];
                float vd = av[rr] * adh[tid];
#pragma unroll
                for (int off = 16; off; off >>= 1) {
                    vs += __shfl_down_sync(0xffffffffu, vs, off);
                    vd += __shfl_down_sync(0xffffffffu, vd, off);
                }
                if (lane == 0) {
                    atomicAdd(&g_as[r * HEADS + head], vs);
                    atomicAdd(&g_ad[r * HEADS + head], vd);
                }
            }
        }
        __syncthreads();
    }
}

// ---------------- per-head global maxes of a_s and a_d ----------------------
__global__ void maxhead_kernel() {
    __shared__ float shs[256], shd[256];
    int tid = threadIdx.x;
    int i   = blockIdx.x * 256 + tid;
    float vs = -3.0e38f, vd = -3.0e38f;
    if (i < NN * HEADS) { vs = g_as[i]; vd = g_ad[i]; }
    shs[tid] = vs; shd[tid] = vd;
    __syncthreads();
#pragma unroll
    for (int off = 128; off >= 4; off >>= 1) {   // offsets stay multiples of 4
        if (tid < off) {
            shs[tid] = fmaxf(shs[tid], shs[tid + off]);
            shd[tid] = fmaxf(shd[tid], shd[tid + off]);
        }
        __syncthreads();
    }
    if (tid < 4) {
        atomicMax(&g_maxenc[tid],     fenc(shs[tid]));
        atomicMax(&g_maxenc[4 + tid], fenc(shd[tid]));
    }
}

__device__ __forceinline__ float lrelu(float e) {
    return (e > 0.f) ? e : 0.2f * e;
}

// ---------------- GAT aggregation: single pass, chain-free ------------------
__global__ void gat_agg_kernel(const float* __restrict__ b_gat) {
    int gt   = blockIdx.x * blockDim.x + threadIdx.x;
    int warp = gt >> 5;
    if (warp >= NN) return;
    int lane = gt & 31;
    int hd   = lane >> 3;                   // head for this lane
    int base = hd * HID + (lane & 7) * 8;   // 8 contiguous features
    float adv = g_ad[warp * HEADS + hd];
    // global per-head upper bound on logits: lrelu(max_s + max_d)
    float M = lrelu(fdec(g_maxenc[hd]) + fdec(g_maxenc[4 + hd]));
    int beg = g_rowptr[warp], end = g_rowptr[warp + 1];
    float s = 0.f;
    float acc[8];
#pragma unroll
    for (int k = 0; k < 8; ++k) acc[k] = 0.f;

    int j = beg;
    for (; j + 4 <= end; j += 4) {
        int s0 = g_csr[j], s1 = g_csr[j + 1], s2 = g_csr[j + 2], s3 = g_csr[j + 3];
        float w0 = __expf(lrelu(g_as[s0 * HEADS + hd] + adv) - M);
        float w1 = __expf(lrelu(g_as[s1 * HEADS + hd] + adv) - M);
        float w2 = __expf(lrelu(g_as[s2 * HEADS + hd] + adv) - M);
        float w3 = __expf(lrelu(g_as[s3 * HEADS + hd] + adv) - M);
        int4 p0 = *(const int4*)(g_hgh + (size_t)s0 * F2 + base);
        int4 p1 = *(const int4*)(g_hgh + (size_t)s1 * F2 + base);
        int4 p2 = *(const int4*)(g_hgh + (size_t)s2 * F2 + base);
        int4 p3 = *(const int4*)(g_hgh + (size_t)s3 * F2 + base);
        s += w0 + w1 + w2 + w3;
        const __half2* h0 = (const __half2*)&p0;
        const __half2* h1 = (const __half2*)&p1;
        const __half2* h2 = (const __half2*)&p2;
        const __half2* h3 = (const __half2*)&p3;
#pragma unroll
        for (int k = 0; k < 4; ++k) {
            float2 a = __half22float2(h0[k]);
            float2 b = __half22float2(h1[k]);
            float2 c = __half22float2(h2[k]);
            float2 d = __half22float2(h3[k]);
            acc[2 * k]     += w0 * a.x + w1 * b.x + w2 * c.x + w3 * d.x;
            acc[2 * k + 1] += w0 * a.y + w1 * b.y + w2 * c.y + w3 * d.y;
        }
    }
    for (; j < end; ++j) {
        int s0 = g_csr[j];
        float w0 = __expf(lrelu(g_as[s0 * HEADS + hd] + adv) - M);
        int4 p0 = *(const int4*)(g_hgh + (size_t)s0 * F2 + base);
        const __half2* h0 = (const __half2*)&p0;
        s += w0;
#pragma unroll
        for (int k = 0; k < 4; ++k) {
            float2 a = __half22float2(h0[k]);
            acc[2 * k]     += w0 * a.x;
            acc[2 * k + 1] += w0 * a.y;
        }
    }
    float inv = 1.f / s;
    float* o = g_out2 + (size_t)warp * F2 + base;
#pragma unroll
    for (int k = 0; k < 8; ++k)
        o[k] = fmaxf(acc[k] * inv + b_gat[base + k], 0.f);
}

// ---------------- GEMM 3: out = out2 @ W_fc + b_fc (50000x256 @ 256x32) -----
__global__ void gemm3_kernel(const float* __restrict__ Wfc,
                             const float* __restrict__ bfc,
                             float* __restrict__ out) {
    __shared__ float Wsh[F2 * DOUT];        // 32 KB
    __shared__ float insh[8 * F2];          //  8 KB
    int tid = threadIdx.x;                  // 256
    for (int q = tid; q < F2 * DOUT; q += 256) Wsh[q] = Wfc[q];
    __syncthreads();
    int rowBase = blockIdx.x * 128;
    int r = tid >> 5, c = tid & 31;
    float bv = bfc[c];
    for (int g = 0; g < 128; g += 8) {
        for (int q = tid; q < 8 * F2; q += 256) {
            int rr = q >> 8, kk = q & 255;
            int row = rowBase + g + rr;
            insh[q] = (row < NN) ? g_out2[(size_t)row * F2 + kk] : 0.f;
        }
        __syncthreads();
        float a = 0.f;
#pragma unroll 8
        for (int k = 0; k < F2; ++k) a += insh[r * F2 + k] * Wsh[k * DOUT + c];
        int row = rowBase + g + r;
        if (row < NN) out[row * DOUT + c] = a + bv;
        __syncthreads();
    }
}

// ---------------- launch ----------------------------------------------------
extern "C" void kernel_launch(void* const* d_in, const int* in_sizes, int n_in,
                              void* d_out, int out_size) {
    const float* x       = (const float*)d_in[0];
    const int*   ei      = (const int*)  d_in[1];   // int32 (JAX x64 off)
    const float* W_gcn   = (const float*)d_in[2];
    const float* b_gcn   = (const float*)d_in[3];
    const float* W_gat   = (const float*)d_in[4];
    const float* att_src = (const float*)d_in[5];
    const float* att_dst = (const float*)d_in[6];
    const float* b_gat   = (const float*)d_in[7];
    const float* W_fc    = (const float*)d_in[8];
    const float* b_fc    = (const float*)d_in[9];
    float*       out     = (float*)d_out;

    init_kernel    <<<(NN * HEADS + 255) / 256, 256>>>();
    deg_kernel     <<<(EE + 255) / 256, 256>>>(ei);
    scan_kernel    <<<1, 1024>>>();
    csr_fill_kernel<<<(ET + 255) / 256, 256>>>(ei);

    gemm1_kernel   <<<(NN * 32 + 255) / 256, 256>>>(x, W_gcn);
    gcn_agg_kernel <<<(NN * 32 + 255) / 256, 256>>>(b_gcn);

    gemm2_kernel   <<<dim3((NN + 63) / 64, 2), 128>>>(W_gat, att_src, att_dst);
    maxhead_kernel <<<(NN * HEADS + 255) / 256, 256>>>();
    gat_agg_kernel <<<(NN * 32 + 255) / 256, 256>>>(b_gat);

    gemm3_kernel   <<<(NN + 127) / 128, 256>>>(W_fc, b_fc, out);
}